// round 10
// baseline (speedup 1.0000x reference)
#include <cuda_runtime.h>
#include <cuda_bf16.h>
#include <cstdint>
#include <cstddef>

typedef __nv_bfloat16 bf16;

#define BATCH 1024
#define SEQ   80
#define EMB   100
#define UNITS 512
#define N3    1536      // 3*UNITS
#define VOCAB 10000
#define ME    10112     // vocab rows padded to 79*128
#define KE    384       // emb split-K padded (3 segs of 100 at 0/128/256)
#define KH    1536      // split-K for K=512 matrices (3*512)
#define MY    (SEQ*BATCH)

// fused step kernel smem: GEMM tiles alias the fp32 exchange tile
// tiles: As 2*8192 + Bs 2*6144 = 28672 B ; Cs: 128*100*4 = 51200 B
#define SMEM_STEP 51200
#define CS_STRIDE 100

// ---------------- scratch (device globals; no allocation allowed) ----------------
__device__ bf16  g_Ae [ME*KE];            // split emb (A for E' gemm)
__device__ bf16  g_Be [N3*KE];            // split Wx1^T
__device__ bf16  g_Bh1[N3*KH];            // split Wh1^T
__device__ bf16  g_Bh2[N3*KH];            // split Wh2^T
__device__ bf16  g_Bx2[N3*KH];            // split Wx2^T
__device__ float g_Ep [(size_t)ME*N3];    // E' = emb @ Wx1
__device__ bf16  g_A2 [2][BATCH*KH];      // split h2, ping-pong (race-free fused writes)
__device__ bf16  g_Y1 [(size_t)MY*KH];    // split ys1 per t (A for L1 step + big gemm)
__device__ float g_Gx2[(size_t)MY*N3];    // ys1 @ Wx2 for all t
__device__ float g_H1 [BATCH*UNITS];
__device__ float g_H2 [BATCH*UNITS];

__device__ __forceinline__ void split2(float x, bf16 &hi, bf16 &lo){
    hi = __float2bfloat16(x);
    lo = __float2bfloat16(x - __bfloat162float(hi));
}

// ---------------- asm wrappers ----------------
__device__ __forceinline__ void cp16(uint32_t dst, const void* src){
    asm volatile("cp.async.cg.shared.global [%0], [%1], 16;" :: "r"(dst), "l"(src));
}
__device__ __forceinline__ void cp_commit(){ asm volatile("cp.async.commit_group;"); }
__device__ __forceinline__ void cp_wait1(){ asm volatile("cp.async.wait_group 1;"); }
__device__ __forceinline__ void cp_wait0(){ asm volatile("cp.async.wait_group 0;"); }

__device__ __forceinline__ void ldsm4(uint32_t* d, uint32_t saddr){
    asm volatile("ldmatrix.sync.aligned.m8n8.x4.shared.b16 {%0,%1,%2,%3}, [%4];"
        : "=r"(d[0]), "=r"(d[1]), "=r"(d[2]), "=r"(d[3]) : "r"(saddr));
}
__device__ __forceinline__ void mma16816(float* c, const uint32_t* a, uint32_t bb0, uint32_t bb1){
    asm volatile("mma.sync.aligned.m16n8k16.row.col.f32.bf16.bf16.f32 "
        "{%0,%1,%2,%3}, {%4,%5,%6,%7}, {%8,%9}, {%0,%1,%2,%3};"
        : "+f"(c[0]), "+f"(c[1]), "+f"(c[2]), "+f"(c[3])
        : "r"(a[0]), "r"(a[1]), "r"(a[2]), "r"(a[3]), "r"(bb0), "r"(bb1));
}

// ---------------- weight / embedding split kernels ----------------
// A layout along K': [hi | hi | lo], B layout: [hi | lo | hi]
// => products hi*hi + hi*lo + lo*hi  (residual lo*lo ~ 2^-16)

__global__ void k_split_emb(const float* __restrict__ emb){
    int idx = blockIdx.x*blockDim.x + threadIdx.x;
    if (idx >= ME*KE) return;
    int row = idx / KE, k = idx % KE;
    int sel = -1; int kk = 0;
    if (row < VOCAB){
        if (k < EMB)                      { sel = 0; kk = k;       }
        else if (k >= 128 && k < 128+EMB) { sel = 0; kk = k - 128; }
        else if (k >= 256 && k < 256+EMB) { sel = 1; kk = k - 256; }
    }
    bf16 out = __float2bfloat16(0.f);
    if (sel >= 0){
        bf16 hi, lo; split2(emb[row*EMB + kk], hi, lo);
        out = (sel == 0) ? hi : lo;
    }
    g_Ae[idx] = out;
}

__global__ void k_split_Be(const float* __restrict__ Wx1){
    int idx = blockIdx.x*blockDim.x + threadIdx.x;
    if (idx >= N3*KE) return;
    int n = idx / KE, k = idx % KE;
    int sel = -1, kk = 0;
    if (k < EMB)                      { sel = 0; kk = k;       }   // hi
    else if (k >= 128 && k < 128+EMB) { sel = 1; kk = k - 128; }   // lo
    else if (k >= 256 && k < 256+EMB) { sel = 0; kk = k - 256; }   // hi
    bf16 out = __float2bfloat16(0.f);
    if (sel >= 0){
        bf16 hi, lo; split2(Wx1[kk*N3 + n], hi, lo);
        out = (sel == 0) ? hi : lo;
    }
    g_Be[idx] = out;
}

__global__ void k_split_B512(const float* __restrict__ W, bf16* __restrict__ out){
    int idx = blockIdx.x*blockDim.x + threadIdx.x;
    if (idx >= N3*KH) return;
    int n = idx / KH, k = idx % KH;
    int sel, kk;
    if (k < 512)       { sel = 0; kk = k;        }   // hi
    else if (k < 1024) { sel = 1; kk = k - 512;  }   // lo
    else               { sel = 0; kk = k - 1024; }   // hi
    bf16 hi, lo; split2(W[kk*N3 + n], hi, lo);
    out[idx] = (sel == 0) ? hi : lo;
}

// ---------------- swizzle (128x32 bf16 tile; c = 16B chunk index 0..3) ----------------
__device__ __forceinline__ int swzoff(int r, int c){
    return r*32 + (((c ^ (r & 3) ^ ((r >> 2) & 3)) & 3) << 3);
}

// ---------------- GEMM 128x128 tile (E' precompute + big batched gemm) ----------------
__global__ void __launch_bounds__(256) k_gemm(
    const bf16* __restrict__ A, const bf16* __restrict__ Bt,
    float* __restrict__ C, int K)
{
    __shared__ __align__(16) bf16 As[2][128*32];
    __shared__ __align__(16) bf16 Bs[2][128*32];

    const int tid  = threadIdx.x;
    const int lane = tid & 31;
    const int warp = tid >> 5;
    const int wm   = warp & 3;
    const int wn   = warp >> 2;
    const long m0  = (long)blockIdx.y * 128;
    const long n0  = (long)blockIdx.x * 128;
    const bf16* Ag = A  + m0 * K;
    const bf16* Bg = Bt + n0 * K;

    uint32_t sA[2], sB[2];
    sA[0] = (uint32_t)__cvta_generic_to_shared(&As[0][0]);
    sA[1] = (uint32_t)__cvta_generic_to_shared(&As[1][0]);
    sB[0] = (uint32_t)__cvta_generic_to_shared(&Bs[0][0]);
    sB[1] = (uint32_t)__cvta_generic_to_shared(&Bs[1][0]);

    float acc[2][8][4];
    #pragma unroll
    for (int i=0;i<2;i++)
        #pragma unroll
        for (int j=0;j<8;j++)
            #pragma unroll
            for (int q=0;q<4;q++) acc[i][j][q] = 0.f;

    const int nk = K >> 5;
    const int qr = tid >> 2, qc = tid & 3;

    #pragma unroll
    for (int i=0;i<2;i++){
        int r = qr + i*64;
        cp16(sA[0] + swzoff(r,qc)*2, Ag + (long)r*K + qc*8);
        cp16(sB[0] + swzoff(r,qc)*2, Bg + (long)r*K + qc*8);
    }
    cp_commit();

    for (int kt = 0; kt < nk; kt++){
        const int s = kt & 1;
        if (kt + 1 < nk){
            #pragma unroll
            for (int i=0;i<2;i++){
                int r = qr + i*64;
                long koff = (long)(kt+1)*32 + qc*8;
                cp16(sA[s^1] + swzoff(r,qc)*2, Ag + (long)r*K + koff);
                cp16(sB[s^1] + swzoff(r,qc)*2, Bg + (long)r*K + koff);
            }
            cp_commit();
            cp_wait1();
        } else {
            cp_wait0();
        }
        __syncthreads();

        #pragma unroll
        for (int kk = 0; kk < 2; kk++){
            uint32_t areg[2][4];
            uint32_t breg[4][4];
            #pragma unroll
            for (int i=0;i<2;i++){
                int r = wm*32 + i*16 + (lane & 15);
                int c = (kk<<1) + (lane >> 4);
                ldsm4(areg[i], sA[s] + (uint32_t)swzoff(r,c)*2);
            }
            #pragma unroll
            for (int g=0; g<4; g++){
                int r = wn*64 + g*16 + (lane & 15);
                int c = (kk<<1) + (lane >> 4);
                ldsm4(breg[g], sB[s] + (uint32_t)swzoff(r,c)*2);
            }
            #pragma unroll
            for (int i=0;i<2;i++)
                #pragma unroll
                for (int j=0;j<8;j++){
                    int g = j >> 1, h = j & 1;
                    mma16816(acc[i][j], areg[i], breg[g][h], breg[g][h+2]);
                }
        }
        __syncthreads();
    }

    #pragma unroll
    for (int i=0;i<2;i++){
        long row = m0 + wm*32 + i*16 + (lane >> 2);
        #pragma unroll
        for (int j=0;j<8;j++){
            long col = n0 + wn*64 + j*8 + ((lane & 3) << 1);
            *(float2*)&C[row*N3 + col]     = make_float2(acc[i][j][0], acc[i][j][1]);
            *(float2*)&C[(row+8)*N3 + col] = make_float2(acc[i][j][2], acc[i][j][3]);
        }
    }
}

// ---------------- fused step GEMM: 128x96 gathered-triple tile -> smem fp32 ----------------
// B tile rows 0..31 = output cols u0..u0+31 (z), 32..63 = 512+u0.. (r), 64..95 = 1024+u0.. (n)
__device__ __forceinline__ void step_gemm_to_smem(
    const bf16* __restrict__ A, const bf16* __restrict__ Bt,
    int m0, int u0,
    uint32_t sA0, uint32_t sA1, uint32_t sB0, uint32_t sB1,
    float* __restrict__ Cs)
{
    const int tid  = threadIdx.x;
    const int lane = tid & 31;
    const int warp = tid >> 5;
    const int wm   = warp & 3;   // 4 m sub-tiles of 32 rows
    const int wn   = warp >> 2;  // 2 n sub-tiles of 48 cols
    const bf16* Ag = A + (size_t)m0 * KH;

    const int qr = tid >> 2, qc = tid & 3;
    // per-thread gathered B row pointers
    const int r0 = qr;                 // 0..63, always < 96
    const int g0 = r0 >> 5;
    const bf16* Bp0 = Bt + (size_t)(u0 + (r0 & 31) + g0*512) * KH;
    const int r1 = qr + 64;            // 64..127, valid if < 96
    const bf16* Bp1 = nullptr;
    if (r1 < 96){
        const int g1 = r1 >> 5;
        Bp1 = Bt + (size_t)(u0 + (r1 & 31) + g1*512) * KH;
    }

    uint32_t sA[2] = {sA0, sA1};
    uint32_t sB[2] = {sB0, sB1};

    float acc[2][6][4];
    #pragma unroll
    for (int i=0;i<2;i++)
        #pragma unroll
        for (int j=0;j<6;j++)
            #pragma unroll
            for (int q=0;q<4;q++) acc[i][j][q] = 0.f;

    // prologue: k-tile 0
    cp16(sA[0] + swzoff(qr,    qc)*2, Ag + (size_t)qr*KH      + qc*8);
    cp16(sA[0] + swzoff(qr+64, qc)*2, Ag + (size_t)(qr+64)*KH + qc*8);
    cp16(sB[0] + swzoff(r0, qc)*2, Bp0 + qc*8);
    if (Bp1) cp16(sB[0] + swzoff(r1, qc)*2, Bp1 + qc*8);
    cp_commit();

    const int nk = KH >> 5;
    for (int kt = 0; kt < nk; kt++){
        const int s = kt & 1;
        if (kt + 1 < nk){
            const int koff = (kt+1)*32 + qc*8;
            cp16(sA[s^1] + swzoff(qr,    qc)*2, Ag + (size_t)qr*KH      + koff);
            cp16(sA[s^1] + swzoff(qr+64, qc)*2, Ag + (size_t)(qr+64)*KH + koff);
            cp16(sB[s^1] + swzoff(r0, qc)*2, Bp0 + koff);
            if (Bp1) cp16(sB[s^1] + swzoff(r1, qc)*2, Bp1 + koff);
            cp_commit();
            cp_wait1();
        } else {
            cp_wait0();
        }
        __syncthreads();

        #pragma unroll
        for (int kk = 0; kk < 2; kk++){
            uint32_t areg[2][4];
            uint32_t breg[3][4];
            #pragma unroll
            for (int i=0;i<2;i++){
                int r = wm*32 + i*16 + (lane & 15);
                int c = (kk<<1) + (lane >> 4);
                ldsm4(areg[i], sA[s] + (uint32_t)swzoff(r,c)*2);
            }
            #pragma unroll
            for (int g=0; g<3; g++){
                int r = wn*48 + g*16 + (lane & 15);
                int c = (kk<<1) + (lane >> 4);
                ldsm4(breg[g], sB[s] + (uint32_t)swzoff(r,c)*2);
            }
            #pragma unroll
            for (int i=0;i<2;i++)
                #pragma unroll
                for (int j=0;j<6;j++){
                    int g = j >> 1, h = j & 1;
                    mma16816(acc[i][j], areg[i], breg[g][h], breg[g][h+2]);
                }
        }
        __syncthreads();   // also makes As/Bs dead -> Cs alias safe after loop
    }

    // dump acc to padded smem tile (row stride CS_STRIDE floats)
    #pragma unroll
    for (int i=0;i<2;i++){
        int row = wm*32 + i*16 + (lane >> 2);
        #pragma unroll
        for (int j=0;j<6;j++){
            int col = wn*48 + j*8 + ((lane & 3) << 1);
            *(float2*)&Cs[row*CS_STRIDE + col]     = make_float2(acc[i][j][0], acc[i][j][1]);
            *(float2*)&Cs[(row+8)*CS_STRIDE + col] = make_float2(acc[i][j][2], acc[i][j][3]);
        }
    }
}

// ---------------- fused step kernels (GEMM + gate in one launch) ----------------
__global__ void __launch_bounds__(256, 1) k_step1(
    const bf16* __restrict__ A,          // Y1[t-1]
    const int* __restrict__ tokens,
    const float* __restrict__ b1,
    int t, bf16* __restrict__ Y1t)
{
    extern __shared__ char dsm[];
    uint32_t sbase = (uint32_t)__cvta_generic_to_shared(dsm);
    float* Cs = (float*)dsm;
    const int m0 = blockIdx.y * 128;
    const int u0 = blockIdx.x * 32;

    step_gemm_to_smem(A, g_Bh1, m0, u0,
                      sbase, sbase + 8192, sbase + 16384, sbase + 16384 + 6144, Cs);
    __syncthreads();

    #pragma unroll 4
    for (int it = 0; it < 16; it++){
        int idx = it*256 + threadIdx.x;      // 0..4095
        int rr = idx >> 5, uu = idx & 31;
        int b = m0 + rr, u = u0 + uu;
        const float* Crow = Cs + rr*CS_STRIDE;
        float hz = Crow[uu]      + b1[N3+u];
        float hr = Crow[32+uu]   + b1[N3+512+u];
        float hn = Crow[64+uu]   + b1[N3+1024+u];
        int tok = tokens[b*SEQ + t];
        const float* e = g_Ep + (size_t)tok*N3;
        float xz = e[u]      + b1[u];
        float xr = e[u+512]  + b1[u+512];
        float xh = e[u+1024] + b1[u+1024];
        float z  = 1.f/(1.f + expf(-(xz+hz)));
        float r  = 1.f/(1.f + expf(-(xr+hr)));
        float hh = tanhf(xh + r*hn);
        int hidx = b*UNITS + u;
        float h  = z*g_H1[hidx] + (1.f-z)*hh;
        g_H1[hidx] = h;
        bf16 hi, lo; split2(h, hi, lo);
        size_t base = (size_t)b*KH;
        Y1t[base + u]        = hi;
        Y1t[base + 512 + u]  = hi;
        Y1t[base + 1024 + u] = lo;
    }
}

__global__ void __launch_bounds__(256, 1) k_step2(
    const bf16* __restrict__ A,          // A2 ping
    const float* __restrict__ b2,
    const float* __restrict__ gx,        // Gx2 chunk t
    bf16* __restrict__ Aout)             // A2 pong
{
    extern __shared__ char dsm[];
    uint32_t sbase = (uint32_t)__cvta_generic_to_shared(dsm);
    float* Cs = (float*)dsm;
    const int m0 = blockIdx.y * 128;
    const int u0 = blockIdx.x * 32;

    step_gemm_to_smem(A, g_Bh2, m0, u0,
                      sbase, sbase + 8192, sbase + 16384, sbase + 16384 + 6144, Cs);
    __syncthreads();

    #pragma unroll 4
    for (int it = 0; it < 16; it++){
        int idx = it*256 + threadIdx.x;
        int rr = idx >> 5, uu = idx & 31;
        int b = m0 + rr, u = u0 + uu;
        const float* Crow = Cs + rr*CS_STRIDE;
        float hz = Crow[uu]      + b2[N3+u];
        float hr = Crow[32+uu]   + b2[N3+512+u];
        float hn = Crow[64+uu]   + b2[N3+1024+u];
        const float* x = gx + (size_t)b*N3;
        float xz = x[u]      + b2[u];
        float xr = x[u+512]  + b2[u+512];
        float xh = x[u+1024] + b2[u+1024];
        float z  = 1.f/(1.f + expf(-(xz+hz)));
        float r  = 1.f/(1.f + expf(-(xr+hr)));
        float hh = tanhf(xh + r*hn);
        int hidx = b*UNITS + u;
        float h  = z*g_H2[hidx] + (1.f-z)*hh;
        g_H2[hidx] = h;
        bf16 hi, lo; split2(h, hi, lo);
        size_t base = (size_t)b*KH;
        Aout[base + u]        = hi;
        Aout[base + 512 + u]  = hi;
        Aout[base + 1024 + u] = lo;
    }
}

// ---------------- t=0 gate-only kernels (gh = 0, hprev = 0) ----------------
__global__ void __launch_bounds__(256) k_gate1_t0(const int* __restrict__ tokens,
                                                  const float* __restrict__ b1,
                                                  bf16* __restrict__ Y1t)
{
    int idx = blockIdx.x*blockDim.x + threadIdx.x;
    int b = idx >> 9, u = idx & 511;
    int tok = tokens[b*SEQ + 0];
    const float* e = g_Ep + (size_t)tok*N3;
    float hz = b1[N3+u], hr = b1[N3+512+u], hn = b1[N3+1024+u];
    float xz = e[u]      + b1[u];
    float xr = e[u+512]  + b1[u+512];
    float xh = e[u+1024] + b1[u+1024];
    float z  = 1.f/(1.f + expf(-(xz+hz)));
    float r  = 1.f/(1.f + expf(-(xr+hr)));
    float hh = tanhf(xh + r*hn);
    float h  = (1.f-z)*hh;
    g_H1[idx] = h;
    bf16 hi, lo; split2(h, hi, lo);
    size_t base = (size_t)b*KH;
    Y1t[base + u]        = hi;
    Y1t[base + 512 + u]  = hi;
    Y1t[base + 1024 + u] = lo;
}

__global__ void __launch_bounds__(256) k_gate2_t0(const float* __restrict__ b2,
                                                  const float* __restrict__ gx,
                                                  bf16* __restrict__ Aout)
{
    int idx = blockIdx.x*blockDim.x + threadIdx.x;
    int b = idx >> 9, u = idx & 511;
    const float* x = gx + (size_t)b*N3;
    float hz = b2[N3+u], hr = b2[N3+512+u], hn = b2[N3+1024+u];
    float xz = x[u]      + b2[u];
    float xr = x[u+512]  + b2[u+512];
    float xh = x[u+1024] + b2[u+1024];
    float z  = 1.f/(1.f + expf(-(xz+hz)));
    float r  = 1.f/(1.f + expf(-(xr+hr)));
    float hh = tanhf(xh + r*hn);
    float h  = (1.f-z)*hh;
    g_H2[idx] = h;
    bf16 hi, lo; split2(h, hi, lo);
    size_t base = (size_t)b*KH;
    Aout[base + u]        = hi;
    Aout[base + 512 + u]  = hi;
    Aout[base + 1024 + u] = lo;
}

// ---------------- final dense + sigmoid ----------------
__global__ void __launch_bounds__(256) k_final(const float* __restrict__ Wfc,
                                               const float* __restrict__ bfc,
                                               float* __restrict__ out)
{
    int gtid = blockIdx.x*blockDim.x + threadIdx.x;
    int w = gtid >> 5, lane = gtid & 31;
    if (w >= BATCH) return;
    float s = 0.f;
    for (int u = lane; u < UNITS; u += 32) s += g_H2[w*UNITS + u] * Wfc[u];
    #pragma unroll
    for (int o = 16; o > 0; o >>= 1) s += __shfl_xor_sync(0xffffffffu, s, o);
    if (lane == 0) out[w] = 1.f/(1.f + expf(-(s + bfc[0])));
}

// ---------------- host ----------------
extern "C" void kernel_launch(void* const* d_in, const int* in_sizes, int n_in,
                              void* d_out, int out_size)
{
    const int*   tokens = (const int*)  d_in[0];
    const float* emb    = (const float*)d_in[1];
    const float* Wx1    = (const float*)d_in[2];
    const float* Wh1    = (const float*)d_in[3];
    const float* b1     = (const float*)d_in[4];
    const float* Wx2    = (const float*)d_in[5];
    const float* Wh2    = (const float*)d_in[6];
    const float* b2     = (const float*)d_in[7];
    const float* Wfc    = (const float*)d_in[8];
    const float* bfc    = (const float*)d_in[9];

    bf16 *pAe, *pBe, *pBh1, *pBh2, *pBx2, *pY1;
    bf16 *pA2base;
    float *pEp, *pGx2;
    cudaGetSymbolAddress((void**)&pAe,  g_Ae);
    cudaGetSymbolAddress((void**)&pBe,  g_Be);
    cudaGetSymbolAddress((void**)&pBh1, g_Bh1);
    cudaGetSymbolAddress((void**)&pBh2, g_Bh2);
    cudaGetSymbolAddress((void**)&pBx2, g_Bx2);
    cudaGetSymbolAddress((void**)&pA2base, g_A2);
    cudaGetSymbolAddress((void**)&pY1,  g_Y1);
    cudaGetSymbolAddress((void**)&pEp,  g_Ep);
    cudaGetSymbolAddress((void**)&pGx2, g_Gx2);
    bf16* pA2[2] = { pA2base, pA2base + (size_t)BATCH*KH };

    static int attr_done = 0;
    if (!attr_done){
        cudaFuncSetAttribute(k_step1, cudaFuncAttributeMaxDynamicSharedMemorySize, SMEM_STEP);
        cudaFuncSetAttribute(k_step2, cudaFuncAttributeMaxDynamicSharedMemorySize, SMEM_STEP);
        attr_done = 1;
    }

    // 1. split weights / embeddings
    k_split_emb <<<(ME*KE + 255)/256, 256>>>(emb);
    k_split_Be  <<<(N3*KE + 255)/256, 256>>>(Wx1);
    k_split_B512<<<(N3*KH + 255)/256, 256>>>(Wh1, pBh1);
    k_split_B512<<<(N3*KH + 255)/256, 256>>>(Wh2, pBh2);
    k_split_B512<<<(N3*KH + 255)/256, 256>>>(Wx2, pBx2);

    // 2. E' = emb @ Wx1  (per-vocab-word precompute)
    k_gemm<<<dim3(12, ME/128), 256>>>(pAe, pBe, pEp, KE);

    // 3. layer-1 recurrence: fused GEMM+gate per step
    dim3 sgrid(16, 8);
    k_gate1_t0<<<(BATCH*UNITS)/256, 256>>>(tokens, b1, pY1);
    for (int t = 1; t < SEQ; t++){
        k_step1<<<sgrid, 256, SMEM_STEP>>>(pY1 + (size_t)(t-1)*BATCH*KH,
                                           tokens, b1, t,
                                           pY1 + (size_t)t*BATCH*KH);
    }

    // 4. batched gx2 = ys1 @ Wx2 for all timesteps
    k_gemm<<<dim3(12, MY/128), 256>>>(pY1, pBx2, pGx2, KH);

    // 5. layer-2 recurrence: fused GEMM+gate per step (ping-pong A2)
    k_gate2_t0<<<(BATCH*UNITS)/256, 256>>>(b2, pGx2, pA2[0]);
    for (int t = 1; t < SEQ; t++){
        k_step2<<<sgrid, 256, SMEM_STEP>>>(pA2[(t-1)&1], b2,
                                           pGx2 + (size_t)t*BATCH*N3,
                                           pA2[t&1]);
    }

    // 6. logits + sigmoid
    k_final<<<BATCH/8, 256>>>(Wfc, bfc, (float*)d_out);
}